// round 2
// baseline (speedup 1.0000x reference)
#include <cuda_runtime.h>
#include <math.h>
#include <stdint.h>

#define TOK   1024   // B*S
#define SLEN  256
#define BATCH 4
#define HID   512
#define DINP  1024
#define GHID  2048
#define NPRE  4096   // 2 dirs * 4H

#define NBLK     64      // blocks per direction in lstm kernel
#define NBLK_TOT 128
#define WT_STRIDE 33

// ---------------- device scratch (static, no allocation) ----------------
__device__ float g_xA[TOK * DINP];
__device__ float g_xB[TOK * DINP];
__device__ float g_pre[TOK * NPRE];
__device__ float g_pa[TOK * HID];
__device__ float g_pb[TOK * HID];
__device__ float g_h[2 * 2 * HID * 4];   // [buf][dir][k][batch]
__device__ unsigned g_bar;

// ---------------- helpers ----------------
__device__ __forceinline__ float sigf(float x) {
    return 1.0f / (1.0f + __expf(-x));
}
__device__ __forceinline__ float tanh_acc(float x) {
    x = fminf(fmaxf(x, -30.0f), 30.0f);
    float e = __expf(-2.0f * x);
    return (1.0f - e) / (1.0f + e);
}
__device__ __forceinline__ float tanh_fast(float x) {
    float y;
    asm("tanh.approx.f32 %0, %1;" : "=f"(y) : "f"(x));
    return y;
}

__global__ void reset_bar_kernel() { g_bar = 0u; }

// ---------------- embedding gather + concat ----------------
__global__ __launch_bounds__(256) void embed_kernel(
    const int* __restrict__ sent, const int* __restrict__ pos,
    const float* __restrict__ emb)
{
    int gid = blockIdx.x * 256 + threadIdx.x;   // over TOK*256 float4s
    int token = gid >> 8;
    int q = gid & 255;
    const float4* src;
    if (q < 128) src = (const float4*)(emb + (size_t)sent[token] * HID) + q;
    else         src = (const float4*)(emb + (size_t)pos[token]  * HID) + (q - 128);
    ((float4*)g_xA)[gid] = *src;
}

// ---------------- fp32 SIMT GEMM: C[M,N] = A[M,K] * B[N,K]^T + bias(n) ----------------
// block tile 64x64, BK=16, 256 threads, 4x4 per thread. M from gridDim.y*64.
__global__ __launch_bounds__(256) void gemm_kernel(
    const float* __restrict__ A, const float* __restrict__ B,
    float* __restrict__ C, int N, int K, int ldb,
    const float* __restrict__ bias1, const float* __restrict__ bias2)
{
    __shared__ float As[16][64];
    __shared__ float Bs[16][64];
    const int tid = threadIdx.x;
    const int bm = blockIdx.y << 6, bn = blockIdx.x << 6;
    const int tx = tid & 15, ty = tid >> 4;
    const int lr = tid >> 2;            // 0..63
    const int lk = (tid & 3) << 2;      // 0,4,8,12

    const float* Ap = A + (size_t)(bm + lr) * K + lk;
    const float* Bp = B + (size_t)(bn + lr) * ldb + lk;

    float acc[4][4];
#pragma unroll
    for (int i = 0; i < 4; i++)
#pragma unroll
        for (int j = 0; j < 4; j++) acc[i][j] = 0.0f;

    for (int k0 = 0; k0 < K; k0 += 16) {
        float4 av = *(const float4*)(Ap + k0);
        float4 bv = *(const float4*)(Bp + k0);
        As[lk + 0][lr] = av.x; As[lk + 1][lr] = av.y;
        As[lk + 2][lr] = av.z; As[lk + 3][lr] = av.w;
        Bs[lk + 0][lr] = bv.x; Bs[lk + 1][lr] = bv.y;
        Bs[lk + 2][lr] = bv.z; Bs[lk + 3][lr] = bv.w;
        __syncthreads();
#pragma unroll
        for (int k = 0; k < 16; k++) {
            float4 a4 = *(const float4*)&As[k][ty << 2];
            float4 b4 = *(const float4*)&Bs[k][tx << 2];
            float aa[4] = {a4.x, a4.y, a4.z, a4.w};
            float bb[4] = {b4.x, b4.y, b4.z, b4.w};
#pragma unroll
            for (int i = 0; i < 4; i++)
#pragma unroll
                for (int j = 0; j < 4; j++)
                    acc[i][j] = fmaf(aa[i], bb[j], acc[i][j]);
        }
        __syncthreads();
    }

#pragma unroll
    for (int j = 0; j < 4; j++) {
        int n = bn + (tx << 2) + j;
        float bb = 0.0f;
        if (bias1) bb += bias1[n];
        if (bias2) bb += bias2[n];
#pragma unroll
        for (int i = 0; i < 4; i++)
            C[(size_t)(bm + (ty << 2) + i) * N + n] = acc[i][j] + bb;
    }
}

// ---------------- grid barrier ----------------
__device__ __forceinline__ void grid_barrier(unsigned target) {
    __threadfence();
    __syncthreads();
    if (threadIdx.x == 0) {
        atomicAdd(&g_bar, 1u);
        while (atomicAdd(&g_bar, 0u) < target) { }
        __threadfence();
    }
    __syncthreads();
}

// ---------------- persistent bidirectional LSTM scan (one layer) ----------------
// grid = 128 blocks: blocks [0,64) = fwd, [64,128) = bwd. Each block owns 8 hidden units.
__global__ __launch_bounds__(256) void lstm_kernel(
    const float* __restrict__ pre,     // [TOK][4096]  (dir*2048 + gate*512 + u), bias folded
    const float* __restrict__ whh,     // [2][2048][512] for this layer
    const int* __restrict__ length,
    float* __restrict__ xout)          // [TOK][1024]: fwd [0:512], bwd [512:1024]
{
    extern __shared__ float sm[];
    float*  Wt   = sm;                                  // 512*33
    float4* hbuf = (float4*)(sm + 512 * WT_STRIDE);     // 512 float4
    float*  red  = (float*)(hbuf + 512);                // 1024
    float*  gsum = red + 1024;                          // 128
    float*  cst  = gsum + 128;                          // 32

    const int tid = threadIdx.x;
    const int d   = blockIdx.x / NBLK;
    const int blk = blockIdx.x % NBLK;
    const int u0  = blk * 8;

    // load W_hh slice transposed: rows = gate*512 + u0 + j, j=0..7, gate=0..3
    const float* wbase = whh + (size_t)d * GHID * HID;
    for (int idx = tid; idx < 32 * 512; idx += 256) {
        int r = idx >> 9;        // 0..31 local row
        int k = idx & 511;
        int row = ((r >> 3) * HID) + u0 + (r & 7);
        Wt[k * WT_STRIDE + r] = wbase[(size_t)row * HID + k];
    }
    // zero h (both buffers) for owned units
    if (tid < 64) {
        int b = tid & 3, uu = (tid >> 2) & 7, buf = tid >> 5;
        g_h[((buf * 2 + d) * HID + u0 + uu) * 4 + b] = 0.0f;
    }
    if (tid < 32) cst[tid] = 0.0f;

    unsigned bt = NBLK_TOT;
    grid_barrier(bt);   // initial: h zeroed everywhere

    const int r  = tid & 31;
    const int kc = tid >> 5;
    const int b32 = tid >> 3, j32 = tid & 7;

    for (int s = 0; s < SLEN; s++) {
        const int t = d ? (SLEN - 1 - s) : s;
        const int cur = s & 1, nxt = cur ^ 1;

        // prefetch pre-activations for owned gates (latency hidden behind matvec)
        float pi = 0, pf = 0, pg = 0, po = 0;
        if (tid < 32) {
            const float* pp = pre + (size_t)(b32 * SLEN + t) * NPRE + d * GHID + u0 + j32;
            pi = pp[0]; pf = pp[512]; pg = pp[1024]; po = pp[1536];
        }

        // load full h (this dir) into smem — must bypass L1 (cross-SM producer)
        const float4* hg = ((const float4*)g_h) + (cur * 2 + d) * HID;
        hbuf[tid]       = __ldcg(hg + tid);
        hbuf[tid + 256] = __ldcg(hg + tid + 256);
        __syncthreads();

        // partial matvec: thread (r, kc): gate-row r over k chunk [kc*64, kc*64+64)
        float a0 = 0, a1 = 0, a2 = 0, a3 = 0;
        const float*  wp = Wt + (kc * 64) * WT_STRIDE + r;
        const float4* hp = hbuf + kc * 64;
#pragma unroll 8
        for (int kk = 0; kk < 64; kk++) {
            float  w  = wp[kk * WT_STRIDE];
            float4 h4 = hp[kk];
            a0 = fmaf(w, h4.x, a0); a1 = fmaf(w, h4.y, a1);
            a2 = fmaf(w, h4.z, a2); a3 = fmaf(w, h4.w, a3);
        }
        red[tid] = a0; red[256 + tid] = a1; red[512 + tid] = a2; red[768 + tid] = a3;
        __syncthreads();

        if (tid < 128) {
            int b = tid >> 5, rr = tid & 31;
            float ssum = 0.0f;
#pragma unroll
            for (int q = 0; q < 8; q++) ssum += red[b * 256 + q * 32 + rr];
            gsum[b * 32 + rr] = ssum;
        }
        __syncthreads();

        if (tid < 32) {
            const int b = b32, j = j32;
            float gi = pi + gsum[b * 32 + 0 * 8 + j];
            float gf = pf + gsum[b * 32 + 1 * 8 + j];
            float gg = pg + gsum[b * 32 + 2 * 8 + j];
            float go = po + gsum[b * 32 + 3 * 8 + j];
            float cold = cst[tid];
            float cn = sigf(gf) * cold + sigf(gi) * tanh_acc(gg);
            float hn = sigf(go) * tanh_acc(cn);
            bool m = (t < length[b]);
            float hold = ((const float*)(hbuf + u0 + j))[b];
            float hnew = m ? hn : hold;
            if (m) cst[tid] = cn;
            __stcg(&((float*)g_h)[((nxt * 2 + d) * HID + u0 + j) * 4 + b], hnew);
            xout[(size_t)(b * SLEN + t) * DINP + d * HID + u0 + j] = m ? hn : 0.0f;
        }

        bt += NBLK_TOT;
        grid_barrier(bt);
    }
}

// ---------------- score: out[b,s,t] = b2 + sum_h w2[h]*tanh(pa[b,s,h]+pbb[b,t,h]) ----------------
__global__ __launch_bounds__(256) void score_kernel(
    const float* __restrict__ pa, const float* __restrict__ pb,
    const float* __restrict__ w2, const float* __restrict__ b2,
    float* __restrict__ out)
{
    extern __shared__ float sm[];
    float* paT = sm;                 // [512][17]
    float* pbT = sm + 512 * 17;
    float* w2s = pbT + 512 * 17;     // [512]

    const int tid = threadIdx.x;
    const int btt = blockIdx.x, bss = blockIdx.y, b = blockIdx.z;

    for (int idx = tid; idx < 16 * 512; idx += 256) {
        int row = idx >> 9, h = idx & 511;
        paT[h * 17 + row] = pa[(size_t)(b * SLEN + bss * 16 + row) * HID + h];
        pbT[h * 17 + row] = pb[(size_t)(b * SLEN + btt * 16 + row) * HID + h];
    }
    for (int idx = tid; idx < 512; idx += 256) w2s[idx] = w2[idx];
    __syncthreads();

    const int si = tid & 15, ti = tid >> 4;
    float acc = 0.0f;
#pragma unroll 8
    for (int h = 0; h < 512; h++) {
        float x = paT[h * 17 + si] + pbT[h * 17 + ti];
        acc = fmaf(w2s[h], tanh_fast(x), acc);
    }
    out[(size_t)(b * SLEN + bss * 16 + si) * SLEN + btt * 16 + ti] = acc + b2[0];
}

// ---------------- launch ----------------
extern "C" void kernel_launch(void* const* d_in, const int* in_sizes, int n_in,
                              void* d_out, int out_size)
{
    const int*   sent   = (const int*)d_in[0];
    const int*   pos    = (const int*)d_in[1];
    const int*   length = (const int*)d_in[2];
    const float* emb    = (const float*)d_in[3];
    const float* w_ih   = (const float*)d_in[4];
    const float* w_hh   = (const float*)d_in[5];
    const float* b_ih   = (const float*)d_in[6];
    const float* b_hh   = (const float*)d_in[7];
    const float* w1     = (const float*)d_in[8];
    const float* b1     = (const float*)d_in[9];
    const float* w2     = (const float*)d_in[10];
    const float* b2     = (const float*)d_in[11];
    float* out = (float*)d_out;

    const int LSTM_SMEM  = 512 * WT_STRIDE * 4 + 512 * 16 + 1024 * 4 + 128 * 4 + 32 * 4;
    const int SCORE_SMEM = 2 * 512 * 17 * 4 + 512 * 4;

    cudaFuncSetAttribute(lstm_kernel,  cudaFuncAttributeMaxDynamicSharedMemorySize, LSTM_SMEM);
    cudaFuncSetAttribute(score_kernel, cudaFuncAttributeMaxDynamicSharedMemorySize, SCORE_SMEM);

    float *xA, *xB, *prep, *pap, *pbp;
    cudaGetSymbolAddress((void**)&xA,   g_xA);
    cudaGetSymbolAddress((void**)&xB,   g_xB);
    cudaGetSymbolAddress((void**)&prep, g_pre);
    cudaGetSymbolAddress((void**)&pap,  g_pa);
    cudaGetSymbolAddress((void**)&pbp,  g_pb);

    embed_kernel<<<1024, 256>>>(sent, pos, emb);

    for (int l = 0; l < 2; l++) {
        const float* Ain = l ? xB : xA;
        float* Xout      = l ? xA : xB;
        // pre = X @ W_ih^T + (b_ih + b_hh),  N = 4096 (2 dirs x 2048), K = 1024
        gemm_kernel<<<dim3(NPRE / 64, TOK / 64), 256>>>(
            Ain, w_ih + (size_t)l * NPRE * DINP, prep,
            NPRE, DINP, DINP, b_ih + l * NPRE, b_hh + l * NPRE);
        reset_bar_kernel<<<1, 1>>>();
        lstm_kernel<<<NBLK_TOT, 256, LSTM_SMEM>>>(
            prep, w_hh + (size_t)l * 2 * GHID * HID, length, Xout);
    }

    // pa = X @ wa^T ; pbb = X @ wb^T + b1   (wa = w1[:, :1024], wb = w1[:, 1024:])
    gemm_kernel<<<dim3(HID / 64, TOK / 64), 256>>>(
        xA, w1,        pap, HID, DINP, 2048, nullptr, nullptr);
    gemm_kernel<<<dim3(HID / 64, TOK / 64), 256>>>(
        xA, w1 + 1024, pbp, HID, DINP, 2048, b1, nullptr);

    score_kernel<<<dim3(16, 16, 4), 256, SCORE_SMEM>>>(pap, pbp, w2, b2, out);
}